// round 8
// baseline (speedup 1.0000x reference)
#include <cuda_runtime.h>
#include <cuda_bf16.h>
#include <cstdint>

#define NF 64
#define NW 64
#define NBATCH 32768
#define ROWS 128
#define NCTA (NBATCH / ROWS)
#define NTHREADS 256

// ---------------- dynamic SMEM layout (offsets from 1024-aligned base) ------
// 4 basis buffers (bufs 0/1 double as X hi/lo staging; region + buf2 head
// doubles as the f32 D matrix in the epilogue). Coef ring OVERLAYS the skip-W
// region: W is dead after the skip GEMM, coef prefetch starts after it.
#define OF_A(b) ((b) * 16384)                 // 4 x 16KB basis tiles, SW128
#define OF_WHI  65536                          // skip W hi (dead after skip GEMM)
#define OF_WLO  73728
#define OF_C(s) (65536 + (s) * 8192)          // coef ring, 4 slots (32KB)
#define OF_D    0                              // f32 D[128][65] overlay (epilogue)
#define DSTRIDE 65
#define DYN_BYTES (98304 + 1024)              // 97KB -> 2 CTAs/SM

// ---------------- device globals (allocation-free scratch) ------------------
__device__ __align__(16) unsigned short g_coefB[NF * 64 * 64];  // bf16, pre-swizzled [f][w][g]

__device__ __forceinline__ unsigned su(const void* p) {
    return (unsigned)__cvta_generic_to_shared(p);
}
__device__ __forceinline__ unsigned short bfbits(float x) {
    __nv_bfloat16 h = __float2bfloat16(x);
    return *reinterpret_cast<unsigned short*>(&h);
}
__device__ __forceinline__ float bfround(float x) {
    return __bfloat162float(__float2bfloat16(x));
}

// ---------------------------------------------------------------------------
// Prep: spline_coeffs [f][g][w] fp32 -> bf16 B-tiles [f][w-row][g-col],
// SW128 pre-swizzled so a linear cp.async lands them ldmatrix-ready.
// ---------------------------------------------------------------------------
__global__ void prep_kernel(const float* __restrict__ coef) {
    int i0 = blockIdx.x * blockDim.x + threadIdx.x;
    int stride = gridDim.x * blockDim.x;
    for (int i = i0; i < NF * 64 * 64; i += stride) {
        int f = i >> 12, rem = i & 4095, g = rem >> 6, w = rem & 63;
        unsigned o = (unsigned)w * 128u + ((2u * (unsigned)g) ^ (((unsigned)w & 7u) << 4));
        g_coefB[(f << 12) + (o >> 1)] = bfbits(coef[i]);
    }
}

// 8KB coef tile f -> SMEM slot via cp.async (2 x 16B per thread, 256 thr)
__device__ __forceinline__ void cpa_coef(char* dynp, int slot, int f, int tid) {
    unsigned dst = su(dynp + OF_C(slot)) + tid * 16;
    const char* src = (const char*)(g_coefB + ((size_t)f << 12)) + tid * 16;
    asm volatile(
        "cp.async.cg.shared.global [%0], [%1], 16;\n\t"
        "cp.async.cg.shared.global [%2], [%3], 16;"
        :: "r"(dst), "l"(src), "r"(dst + 4096), "l"(src + 4096) : "memory");
}

__device__ __forceinline__ void hmma(float (&c)[4], const unsigned (&a)[4],
                                     const unsigned (&b)[2]) {
    asm volatile(
        "mma.sync.aligned.m16n8k16.row.col.f32.bf16.bf16.f32 "
        "{%0,%1,%2,%3}, {%4,%5,%6,%7}, {%8,%9}, {%0,%1,%2,%3};"
        : "+f"(c[0]), "+f"(c[1]), "+f"(c[2]), "+f"(c[3])
        : "r"(a[0]), "r"(a[1]), "r"(a[2]), "r"(a[3]), "r"(b[0]), "r"(b[1]));
}

// One 128x64 @ 64x64 -> 128x64 GEMM step, 8 warps, warp tile 32x32.
// A tile: [row][k] bf16, 128B rows, SW128.  B tile: [n][k] bf16, 128B rows, SW128.
__device__ __forceinline__ void gemm64(unsigned abase, unsigned bbase, int lane,
                                       int wr, int wc, float (&acc)[2][4][4]) {
    const unsigned sw = (unsigned)(lane & 7) << 4;
    const unsigned arow = (unsigned)(wr * 32 + (lane & 7) + ((lane >> 3) & 1) * 8);
    const unsigned ac16 = (unsigned)((lane >> 4) << 4);
    const unsigned brow = (unsigned)(wc * 32 + (lane & 7));
    const unsigned bc16 = (unsigned)(((lane >> 3) & 1) << 4);
#pragma unroll
    for (int ks = 0; ks < 4; ks++) {
        unsigned acol = ((unsigned)(ks * 32) + ac16) ^ sw;
        unsigned bcol = ((unsigned)(ks * 32) + bc16) ^ sw;
        unsigned b[4][2];
#pragma unroll
        for (int nt = 0; nt < 4; nt++) {
            unsigned addr = bbase + (brow + nt * 8) * 128u + bcol;
            asm volatile(
                "ldmatrix.sync.aligned.m8n8.x2.shared.b16 {%0,%1}, [%2];"
                : "=r"(b[nt][0]), "=r"(b[nt][1]) : "r"(addr));
        }
#pragma unroll
        for (int mt = 0; mt < 2; mt++) {
            unsigned a[4];
            unsigned addr = abase + (arow + mt * 16) * 128u + acol;
            asm volatile(
                "ldmatrix.sync.aligned.m8n8.x4.shared.b16 {%0,%1,%2,%3}, [%4];"
                : "=r"(a[0]), "=r"(a[1]), "=r"(a[2]), "=r"(a[3]) : "r"(addr));
#pragma unroll
            for (int nt = 0; nt < 4; nt++) hmma(acc[mt][nt], a, b[nt]);
        }
    }
}

// Basis writer: 4 cubic B-spline nonzeros packed into a word-aligned 3-u32
// window (slack slots are true zeros); clears this buffer's previous window.
__device__ __forceinline__ void write_basis(char* Ab, unsigned rx,
                                            const float* xcol, int fb,
                                            const float* sh_s, const float* sc_s,
                                            const float* kn, const float* rcp6,
                                            int& pw) {
    if (pw >= 0) {
        *(unsigned*)(Ab + ((unsigned)(pw + 0) ^ rx)) = 0;
        *(unsigned*)(Ab + ((unsigned)(pw + 4) ^ rx)) = 0;
        if (pw + 8 < 128) *(unsigned*)(Ab + ((unsigned)(pw + 8) ^ rx)) = 0;
    }
    float xv = __ldg(xcol + fb);
    float arg = (xv - sh_s[fb]) * sc_s[fb];
    float xs = __fdividef(1.0f, 1.0f + __expf(-arg));
    int jj = (int)(xs * 61.0f);
    jj = jj < 60 ? jj : 60;
    jj = jj < 0 ? 0 : jj;
    const int j = jj + 3;
    const float* rc = &rcp6[jj * 6];
    float l1 = xs - kn[j], l2 = xs - kn[j - 1], l3 = xs - kn[j - 2];
    float r1 = kn[j + 1] - xs, r2 = kn[j + 2] - xs, r3 = kn[j + 3] - xs;
    float t = rc[0];
    float N0 = r1 * t, N1 = l1 * t;
    t = N0 * rc[1]; N0 = r1 * t; float sv = l2 * t;
    t = N1 * rc[2]; N1 = sv + r2 * t; float N2 = l1 * t;
    t = N0 * rc[3]; N0 = r1 * t; sv = l3 * t;
    t = N1 * rc[4]; N1 = sv + r2 * t; sv = l2 * t;
    t = N2 * rc[5]; N2 = sv + r3 * t; float N3 = l1 * t;
    unsigned b0 = bfbits(N0), b1 = bfbits(N1);
    unsigned b2 = bfbits(N2), b3 = bfbits(N3);
    int wb = (jj >> 1) * 4;
    unsigned w0, w1, w2;
    if (jj & 1) { w0 = b0 << 16; w1 = b1 | (b2 << 16); w2 = b3; }
    else        { w0 = b0 | (b1 << 16); w1 = b2 | (b3 << 16); w2 = 0; }
    *(unsigned*)(Ab + ((unsigned)(wb + 0) ^ rx)) = w0;
    *(unsigned*)(Ab + ((unsigned)(wb + 4) ^ rx)) = w1;
    if (wb + 8 < 128) *(unsigned*)(Ab + ((unsigned)(wb + 8) ^ rx)) = w2;
    pw = wb;
}

// ---------------------------------------------------------------------------
// Fused KAN layer on mma.sync, 2 CTAs/SM x 8 warps, software-pipelined:
//   per iteration (2 features): thread-half 0 writes basis f+2, half 1 writes
//   f+3 (idle buffer pair), then all 8 warps GEMM features f,f+1 written last
//   iteration; ONE __syncthreads per pair. Two CTAs per SM decorrelate the
//   barrier drains so the SM always has issuable warps.
// ---------------------------------------------------------------------------
__global__ void __launch_bounds__(NTHREADS, 2) kan_kernel(
    const float* __restrict__ X,
    const float* __restrict__ shift,
    const float* __restrict__ lscale,
    const float* __restrict__ skipW,
    const float* __restrict__ skip_b,
    const float* __restrict__ bias,
    const float* __restrict__ gamma,
    const float* __restrict__ beta,
    const float* __restrict__ knots,
    float* __restrict__ out) {
    extern __shared__ char dynraw[];
    char* dynp = (char*)((((uintptr_t)dynraw) + 1023) & ~(uintptr_t)1023);

    __shared__ float kn[68], rcp6[61 * 6];
    __shared__ float sh_s[64], sc_s[64], cb_s[64], ga_s[64], be_s[64];

    const int tid = threadIdx.x;
    const int lane = tid & 31;
    const int wid = tid >> 5;
    const int wr = wid >> 1, wc = wid & 1;
    const int rgbase = blockIdx.x * ROWS;

    if (tid < 68) kn[tid] = knots[tid];
    if (tid < 64) {
        sh_s[tid] = shift[tid];
        sc_s[tid] = log1pf(__expf(lscale[tid])) + 0.001f;  // softplus + 1e-3
        cb_s[tid] = skip_b[tid] + bias[tid];
        ga_s[tid] = gamma[tid];
        be_s[tid] = beta[tid];
    }
    __syncthreads();
    if (tid < 61) {
        int j = tid + 3;
        rcp6[tid * 6 + 0] = 1.0f / (kn[j + 1] - kn[j]);
        rcp6[tid * 6 + 1] = 1.0f / (kn[j + 1] - kn[j - 1]);
        rcp6[tid * 6 + 2] = 1.0f / (kn[j + 2] - kn[j]);
        rcp6[tid * 6 + 3] = 1.0f / (kn[j + 1] - kn[j - 2]);
        rcp6[tid * 6 + 4] = 1.0f / (kn[j + 2] - kn[j - 1]);
        rcp6[tid * 6 + 5] = 1.0f / (kn[j + 3] - kn[j]);
    }

    const int rowo = tid & 127;            // owned row (two threads per row)
    const int fsel = tid >> 7;             // 0 or 1: which feature of a pair
    const unsigned rx = (unsigned)(rowo & 7) << 4;

    // ---- stage X hi/lo tiles (A layout, SW128) into bufs 0/1 ----
    {
        const float4* xr4 = reinterpret_cast<const float4*>(X + (size_t)(rgbase + rowo) * NF);
        char* xhb = dynp + OF_A(0) + rowo * 128;
        char* xlb = dynp + OF_A(1) + rowo * 128;
        int q0 = fsel * 8;
#pragma unroll
        for (int qq = 0; qq < 8; qq++) {
            int q = q0 + qq;
            float4 v = xr4[q];
            float hx = bfround(v.x), hy = bfround(v.y);
            float hz = bfround(v.z), hw = bfround(v.w);
            unsigned h0 = (unsigned)bfbits(hx) | ((unsigned)bfbits(hy) << 16);
            unsigned h1 = (unsigned)bfbits(hz) | ((unsigned)bfbits(hw) << 16);
            unsigned l0 = (unsigned)bfbits(v.x - hx) | ((unsigned)bfbits(v.y - hy) << 16);
            unsigned l1 = (unsigned)bfbits(v.z - hz) | ((unsigned)bfbits(v.w - hw) << 16);
            unsigned o0 = (unsigned)(8 * q) ^ rx;
            unsigned o1 = (unsigned)(8 * q + 4) ^ rx;
            *(unsigned*)(xhb + o0) = h0;
            *(unsigned*)(xhb + o1) = h1;
            *(unsigned*)(xlb + o0) = l0;
            *(unsigned*)(xlb + o1) = l1;
        }
    }
    // ---- stage skip_W hi/lo (B layout [w][f], SW128) ----
    for (int idx = tid; idx < 4096; idx += NTHREADS) {
        int w = idx >> 6, fcol = idx & 63;
        float v = skipW[idx];               // skip_W is [W][F] row-major
        float h = bfround(v);
        unsigned o = (unsigned)w * 128u + ((2u * (unsigned)fcol) ^ (((unsigned)w & 7u) << 4));
        *(unsigned short*)(dynp + OF_WHI + o) = bfbits(h);
        *(unsigned short*)(dynp + OF_WLO + o) = bfbits(v - h);
    }
    // ---- zero basis bufs 2,3 (disjoint from X staging and W) ----
    {
        uint4 z = {0, 0, 0, 0};
        uint4* a2 = reinterpret_cast<uint4*>(dynp + OF_A(2));
        for (int i = tid; i < 2048; i += NTHREADS) a2[i] = z;
    }
    __syncthreads();

    float acc[2][4][4];
#pragma unroll
    for (int mt = 0; mt < 2; mt++)
#pragma unroll
        for (int nt = 0; nt < 4; nt++)
#pragma unroll
            for (int e = 0; e < 4; e++) acc[mt][nt][e] = 0.f;

    // ---- skip GEMM: Xhi@Whi + Xhi@Wlo + Xlo@Whi (W region dies after this) ----
    gemm64(su(dynp + OF_A(0)), su(dynp + OF_WHI), lane, wr, wc, acc);
    gemm64(su(dynp + OF_A(0)), su(dynp + OF_WLO), lane, wr, wc, acc);
    gemm64(su(dynp + OF_A(1)), su(dynp + OF_WHI), lane, wr, wc, acc);
    __syncthreads();  // X + W reads done before regions are reused

    // zero basis bufs 0,1 (were X staging)
    {
        uint4 z = {0, 0, 0, 0};
        uint4* a0 = reinterpret_cast<uint4*>(dynp + OF_A(0));
        for (int i = tid; i < 2048; i += NTHREADS) a0[i] = z;
    }
    __syncthreads();

    // coef prefetch pair (0,1) into slots 0,1 (overlaying dead W region)
    cpa_coef(dynp, 0, 0, tid);
    cpa_coef(dynp, 1, 1, tid);
    asm volatile("cp.async.commit_group;");

    // This thread writes basis for feature pairs into buffers fsel / fsel+2.
    int pwA = -1, pwB = -1;
    const float* xcol = X + (size_t)(rgbase + rowo) * NF;
    char* AbA = dynp + OF_A(fsel) + rowo * 128;       // buf 0 or 1
    char* AbB = dynp + OF_A(fsel + 2) + rowo * 128;   // buf 2 or 3

    // prologue: basis f=0 -> buf0 (threads 0-127), f=1 -> buf1 (128-255)
    write_basis(AbA, rx, xcol, fsel, sh_s, sc_s, kn, rcp6, pwA);
    __syncthreads();

    for (int f = 0; f < NF; f += 2) {
        const int bsel = (f >> 1) & 1;  // 0: pair in bufs/slots {0,1}; 1: {2,3}
        // prefetch coef pair (f+2, f+3) into the OTHER slot pair (freed at f-2)
        if (f + 2 < NF) {
            int ps = bsel ? 0 : 2;
            cpa_coef(dynp, ps, f + 2, tid);
            cpa_coef(dynp, ps + 1, f + 3, tid);
        }
        asm volatile("cp.async.commit_group;");

        // write basis for feature f+2+fsel into the idle buffer pair
        if (f + 2 < NF) {
            if (bsel) write_basis(AbA, rx, xcol, f + 2 + fsel, sh_s, sc_s, kn, rcp6, pwA);
            else      write_basis(AbB, rx, xcol, f + 2 + fsel, sh_s, sc_s, kn, rcp6, pwB);
        }

        asm volatile("cp.async.wait_group 1;");   // coef f, f+1 resident

        // GEMM features f, f+1 (basis written last iteration, coef from ring)
        unsigned ab = su(dynp + OF_A(0)) + (unsigned)bsel * 32768u;
        unsigned cb = su(dynp + OF_C(0)) + (unsigned)bsel * 16384u;
        gemm64(ab, cb, lane, wr, wc, acc);
        gemm64(ab + 16384u, cb + 8192u, lane, wr, wc, acc);

        __syncthreads();   // single barrier: orders this iter's writes vs next reads
    }

    // ---- epilogue: accs -> SMEM D (stride-65 f32), LN + GELU ----
    {
        float* D = (float*)(dynp + OF_D);
        int g = lane >> 2, t2 = (lane & 3) * 2;
#pragma unroll
        for (int mt = 0; mt < 2; mt++)
#pragma unroll
            for (int nt = 0; nt < 4; nt++) {
                int r0 = wr * 32 + mt * 16 + g;
                int c0 = wc * 32 + nt * 8 + t2;
                D[r0 * DSTRIDE + c0]           = acc[mt][nt][0];
                D[r0 * DSTRIDE + c0 + 1]       = acc[mt][nt][1];
                D[(r0 + 8) * DSTRIDE + c0]     = acc[mt][nt][2];
                D[(r0 + 8) * DSTRIDE + c0 + 1] = acc[mt][nt][3];
            }
    }
    __syncthreads();

    {
        const int r = tid >> 1, half = tid & 1, cb2 = half * 32;
        const float* Dp = (float*)(dynp + OF_D) + r * DSTRIDE + cb2;
        float y[32];
        float s = 0.f, sq = 0.f;
#pragma unroll
        for (int c = 0; c < 32; c++) {
            float v = Dp[c] + cb_s[cb2 + c];
            y[c] = v;
            s += v;
            sq += v * v;
        }
        s += __shfl_xor_sync(0xffffffffu, s, 1);
        sq += __shfl_xor_sync(0xffffffffu, sq, 1);
        float mean = s * (1.0f / 64.0f);
        float var = sq * (1.0f / 64.0f) - mean * mean;
        var = fmaxf(var, 0.0f);
        float inv = rsqrtf(var + 1e-5f);

        float4* og = reinterpret_cast<float4*>(out + (size_t)(rgbase + r) * NW + cb2);
#pragma unroll
        for (int q = 0; q < 8; q++) {
            float z0 = (y[4 * q + 0] - mean) * inv * ga_s[cb2 + 4 * q + 0] + be_s[cb2 + 4 * q + 0];
            float z1 = (y[4 * q + 1] - mean) * inv * ga_s[cb2 + 4 * q + 1] + be_s[cb2 + 4 * q + 1];
            float z2 = (y[4 * q + 2] - mean) * inv * ga_s[cb2 + 4 * q + 2] + be_s[cb2 + 4 * q + 2];
            float z3 = (y[4 * q + 3] - mean) * inv * ga_s[cb2 + 4 * q + 3] + be_s[cb2 + 4 * q + 3];
            float4 o;
            o.x = 0.5f * z0 * (1.0f + erff(z0 * 0.70710678118654752f));
            o.y = 0.5f * z1 * (1.0f + erff(z1 * 0.70710678118654752f));
            o.z = 0.5f * z2 * (1.0f + erff(z2 * 0.70710678118654752f));
            o.w = 0.5f * z3 * (1.0f + erff(z3 * 0.70710678118654752f));
            og[q] = o;
        }
    }
}

extern "C" void kernel_launch(void* const* d_in, const int* in_sizes, int n_in,
                              void* d_out, int out_size) {
    const float* X      = (const float*)d_in[0];
    const float* shift  = (const float*)d_in[1];
    const float* lscale = (const float*)d_in[2];
    const float* coef   = (const float*)d_in[3];
    const float* skipW  = (const float*)d_in[4];
    const float* skipb  = (const float*)d_in[5];
    const float* bias   = (const float*)d_in[6];
    const float* gam    = (const float*)d_in[7];
    const float* bet    = (const float*)d_in[8];
    const float* knots  = (const float*)d_in[9];

    cudaFuncSetAttribute(kan_kernel, cudaFuncAttributeMaxDynamicSharedMemorySize,
                         DYN_BYTES);

    prep_kernel<<<256, 256>>>(coef);
    kan_kernel<<<NCTA, NTHREADS, DYN_BYTES>>>(X, shift, lscale, skipW, skipb,
                                              bias, gam, bet, knots,
                                              (float*)d_out);
}

// round 9
// speedup vs baseline: 1.0431x; 1.0431x over previous
#include <cuda_runtime.h>
#include <cuda_bf16.h>
#include <cstdint>

#define NF 64
#define NW 64
#define NBATCH 32768
#define ROWS 128
#define NCTA (NBATCH / ROWS)
#define NTHREADS 256

// ---------------- dynamic SMEM layout (offsets from 1024-aligned base) ------
// A0/A1: basis tiles (even/odd feature), warp-private 16-row slices; they
// double as X hi/lo staging for the skip GEMM. Coef ring: 8 slots; the skip-W
// tiles overlay slots 4/5 (dead before those slots are first written).
#define OF_A0   0
#define OF_A1   16384
#define OF_C(s) (32768 + (s) * 8192)    // 8 x 8KB, through 98304
#define OF_WHI  OF_C(4)
#define OF_WLO  OF_C(5)
#define DYN_BYTES (98304 + 1024)        // ~97KB -> 2 CTAs/SM

// ---------------- device globals (allocation-free scratch) ------------------
__device__ __align__(16) unsigned short g_coefB[NF * 64 * 64];  // bf16, pre-swizzled [f][w][g]

__device__ __forceinline__ unsigned su(const void* p) {
    return (unsigned)__cvta_generic_to_shared(p);
}
__device__ __forceinline__ unsigned short bfbits(float x) {
    __nv_bfloat16 h = __float2bfloat16(x);
    return *reinterpret_cast<unsigned short*>(&h);
}
__device__ __forceinline__ float bfround(float x) {
    return __bfloat162float(__float2bfloat16(x));
}

// ---------------------------------------------------------------------------
// Prep: spline_coeffs [f][g][w] fp32 -> bf16 B-tiles [f][w-row][g-col],
// SW128 pre-swizzled so a linear cp.async lands them ldmatrix-ready.
// ---------------------------------------------------------------------------
__global__ void prep_kernel(const float* __restrict__ coef) {
    int i0 = blockIdx.x * blockDim.x + threadIdx.x;
    int stride = gridDim.x * blockDim.x;
    for (int i = i0; i < NF * 64 * 64; i += stride) {
        int f = i >> 12, rem = i & 4095, g = rem >> 6, w = rem & 63;
        unsigned o = (unsigned)w * 128u + ((2u * (unsigned)g) ^ (((unsigned)w & 7u) << 4));
        g_coefB[(f << 12) + (o >> 1)] = bfbits(coef[i]);
    }
}

// 8KB coef tile f -> SMEM slot via cp.async (2 x 16B per thread, 256 thr)
__device__ __forceinline__ void cpa_coef(char* dynp, int slot, int f, int tid) {
    unsigned dst = su(dynp + OF_C(slot)) + tid * 16;
    const char* src = (const char*)(g_coefB + ((size_t)f << 12)) + tid * 16;
    asm volatile(
        "cp.async.cg.shared.global [%0], [%1], 16;\n\t"
        "cp.async.cg.shared.global [%2], [%3], 16;"
        :: "r"(dst), "l"(src), "r"(dst + 4096), "l"(src + 4096) : "memory");
}

__device__ __forceinline__ void hmma(float (&c)[4], const unsigned (&a)[4],
                                     unsigned b0, unsigned b1) {
    asm volatile(
        "mma.sync.aligned.m16n8k16.row.col.f32.bf16.bf16.f32 "
        "{%0,%1,%2,%3}, {%4,%5,%6,%7}, {%8,%9}, {%0,%1,%2,%3};"
        : "+f"(c[0]), "+f"(c[1]), "+f"(c[2]), "+f"(c[3])
        : "r"(a[0]), "r"(a[1]), "r"(a[2]), "r"(a[3]), "r"(b0), "r"(b1));
}

// Warp-private GEMM step: 16x64 warp tile. abase_w already points at this
// warp's 16-row slice. A tile: [row][k] bf16 SW128. B tile: [n][k] bf16 SW128.
__device__ __forceinline__ void gemm16(unsigned abase_w, unsigned bbase, int lane,
                                       float (&acc)[8][4]) {
    const unsigned sw = (unsigned)(lane & 7) << 4;
    const unsigned arow = (unsigned)((lane & 7) + ((lane >> 3) & 1) * 8) * 128u;
    const unsigned ac16 = (unsigned)((lane >> 4) << 4);
    const unsigned brow = (unsigned)((lane & 7) + ((lane >> 4) & 1) * 8) * 128u;
    const unsigned bk16 = (unsigned)(((lane >> 3) & 1) << 4);
#pragma unroll
    for (int ks = 0; ks < 4; ks++) {
        unsigned a[4];
        unsigned aaddr = abase_w + arow + ((ac16 + ks * 32) ^ sw);
        asm volatile(
            "ldmatrix.sync.aligned.m8n8.x4.shared.b16 {%0,%1,%2,%3}, [%4];"
            : "=r"(a[0]), "=r"(a[1]), "=r"(a[2]), "=r"(a[3]) : "r"(aaddr));
#pragma unroll
        for (int t = 0; t < 4; t++) {
            unsigned b0, b1, b2, b3;
            unsigned baddr = bbase + brow + (unsigned)(t * 2048) + ((bk16 + ks * 32) ^ sw);
            asm volatile(
                "ldmatrix.sync.aligned.m8n8.x4.shared.b16 {%0,%1,%2,%3}, [%4];"
                : "=r"(b0), "=r"(b1), "=r"(b2), "=r"(b3) : "r"(baddr));
            hmma(acc[2 * t], a, b0, b1);
            hmma(acc[2 * t + 1], a, b2, b3);
        }
    }
}

// Basis writer: 4 cubic B-spline nonzeros packed into a word-aligned 3-u32
// window (slack slots true zeros); clears this thread's previous window.
__device__ __forceinline__ void write_basis(char* Ab, unsigned rx,
                                            const float* xcol, int fb,
                                            const float* sh_s, const float* sc_s,
                                            const float* kn, const float* rcp6,
                                            int& pw) {
    if (pw >= 0) {
        *(unsigned*)(Ab + ((unsigned)(pw + 0) ^ rx)) = 0;
        *(unsigned*)(Ab + ((unsigned)(pw + 4) ^ rx)) = 0;
        if (pw + 8 < 128) *(unsigned*)(Ab + ((unsigned)(pw + 8) ^ rx)) = 0;
    }
    float xv = __ldg(xcol + fb);
    float arg = (xv - sh_s[fb]) * sc_s[fb];
    float xs = __fdividef(1.0f, 1.0f + __expf(-arg));
    int jj = (int)(xs * 61.0f);
    jj = jj < 60 ? jj : 60;
    jj = jj < 0 ? 0 : jj;
    const int j = jj + 3;
    const float* rc = &rcp6[jj * 6];
    float l1 = xs - kn[j], l2 = xs - kn[j - 1], l3 = xs - kn[j - 2];
    float r1 = kn[j + 1] - xs, r2 = kn[j + 2] - xs, r3 = kn[j + 3] - xs;
    float t = rc[0];
    float N0 = r1 * t, N1 = l1 * t;
    t = N0 * rc[1]; N0 = r1 * t; float sv = l2 * t;
    t = N1 * rc[2]; N1 = sv + r2 * t; float N2 = l1 * t;
    t = N0 * rc[3]; N0 = r1 * t; sv = l3 * t;
    t = N1 * rc[4]; N1 = sv + r2 * t; sv = l2 * t;
    t = N2 * rc[5]; N2 = sv + r3 * t; float N3 = l1 * t;
    unsigned b0 = bfbits(N0), b1 = bfbits(N1);
    unsigned b2 = bfbits(N2), b3 = bfbits(N3);
    int wb = (jj >> 1) * 4;
    unsigned w0, w1, w2;
    if (jj & 1) { w0 = b0 << 16; w1 = b1 | (b2 << 16); w2 = b3; }
    else        { w0 = b0 | (b1 << 16); w1 = b2 | (b3 << 16); w2 = 0; }
    *(unsigned*)(Ab + ((unsigned)(wb + 0) ^ rx)) = w0;
    *(unsigned*)(Ab + ((unsigned)(wb + 4) ^ rx)) = w1;
    if (wb + 8 < 128) *(unsigned*)(Ab + ((unsigned)(wb + 8) ^ rx)) = w2;
    pw = wb;
}

// ---------------------------------------------------------------------------
// Fused KAN layer, warp-decoupled: warp tile 16x64 so each warp's A-slice is
// written AND read only by itself (syncwarp, no CTA barrier). One
// __syncthreads per 4 features (coef ring handoff only). LN+GELU epilogue
// straight from registers (shfl over the 4-thread row group, direct STG).
// ---------------------------------------------------------------------------
__global__ void __launch_bounds__(NTHREADS, 2) kan_kernel(
    const float* __restrict__ X,
    const float* __restrict__ shift,
    const float* __restrict__ lscale,
    const float* __restrict__ skipW,
    const float* __restrict__ skip_b,
    const float* __restrict__ bias,
    const float* __restrict__ gamma,
    const float* __restrict__ beta,
    const float* __restrict__ knots,
    float* __restrict__ out) {
    extern __shared__ char dynraw[];
    char* dynp = (char*)((((uintptr_t)dynraw) + 1023) & ~(uintptr_t)1023);

    __shared__ float kn[68], rcp6[61 * 6];
    __shared__ float sh_s[64], sc_s[64], cb_s[64], ga_s[64], be_s[64];

    const int tid = threadIdx.x;
    const int lane = tid & 31;
    const int wid = tid >> 5;
    const int rgbase = blockIdx.x * ROWS;

    // early coef prefetch: slots 0-3 = features 0-3
    cpa_coef(dynp, 0, 0, tid);
    cpa_coef(dynp, 1, 1, tid);
    cpa_coef(dynp, 2, 2, tid);
    cpa_coef(dynp, 3, 3, tid);
    asm volatile("cp.async.commit_group;");

    if (tid < 68) kn[tid] = knots[tid];
    if (tid < 64) {
        sh_s[tid] = shift[tid];
        sc_s[tid] = log1pf(__expf(lscale[tid])) + 0.001f;  // softplus + 1e-3
        cb_s[tid] = skip_b[tid] + bias[tid];
        ga_s[tid] = gamma[tid];
        be_s[tid] = beta[tid];
    }
    __syncthreads();
    if (tid < 61) {
        int j = tid + 3;
        rcp6[tid * 6 + 0] = 1.0f / (kn[j + 1] - kn[j]);
        rcp6[tid * 6 + 1] = 1.0f / (kn[j + 1] - kn[j - 1]);
        rcp6[tid * 6 + 2] = 1.0f / (kn[j + 2] - kn[j]);
        rcp6[tid * 6 + 3] = 1.0f / (kn[j + 1] - kn[j - 2]);
        rcp6[tid * 6 + 4] = 1.0f / (kn[j + 2] - kn[j - 1]);
        rcp6[tid * 6 + 5] = 1.0f / (kn[j + 3] - kn[j]);
    }

    const int rowo = wid * 16 + (lane & 15);   // warp-private row
    const int half = lane >> 4;                // 0/1: col-half & feature select
    const unsigned rx = (unsigned)(lane & 7) << 4;

    // ---- stage X hi/lo tiles (warp-private rows) into A0/A1 ----
    {
        const float4* xr4 = reinterpret_cast<const float4*>(X + (size_t)(rgbase + rowo) * NF);
        char* xhb = dynp + OF_A0 + rowo * 128;
        char* xlb = dynp + OF_A1 + rowo * 128;
#pragma unroll
        for (int qq = 0; qq < 8; qq++) {
            int q = half * 8 + qq;
            float4 v = xr4[q];
            float hx = bfround(v.x), hy = bfround(v.y);
            float hz = bfround(v.z), hw = bfround(v.w);
            unsigned h0 = (unsigned)bfbits(hx) | ((unsigned)bfbits(hy) << 16);
            unsigned h1 = (unsigned)bfbits(hz) | ((unsigned)bfbits(hw) << 16);
            unsigned l0 = (unsigned)bfbits(v.x - hx) | ((unsigned)bfbits(v.y - hy) << 16);
            unsigned l1 = (unsigned)bfbits(v.z - hz) | ((unsigned)bfbits(v.w - hw) << 16);
            unsigned o0 = (unsigned)(8 * q) ^ rx;
            unsigned o1 = (unsigned)(8 * q + 4) ^ rx;
            *(unsigned*)(xhb + o0) = h0;
            *(unsigned*)(xhb + o1) = h1;
            *(unsigned*)(xlb + o0) = l0;
            *(unsigned*)(xlb + o1) = l1;
        }
    }
    // ---- stage skip_W hi/lo (B layout [w][f], SW128; overlays coef slots 4/5) ----
    for (int idx = tid; idx < 4096; idx += NTHREADS) {
        int w = idx >> 6, fcol = idx & 63;
        float v = skipW[idx];               // skip_W is [W][F] row-major
        float h = bfround(v);
        unsigned o = (unsigned)w * 128u + ((2u * (unsigned)fcol) ^ (((unsigned)w & 7u) << 4));
        *(unsigned short*)(dynp + OF_WHI + o) = bfbits(h);
        *(unsigned short*)(dynp + OF_WLO + o) = bfbits(v - h);
    }
    __syncthreads();   // W + X visible (X is warp-local anyway)

    float acc[8][4];
#pragma unroll
    for (int nt = 0; nt < 8; nt++)
#pragma unroll
        for (int e = 0; e < 4; e++) acc[nt][e] = 0.f;

    const unsigned aw0 = su(dynp + OF_A0) + (unsigned)wid * 2048u;
    const unsigned aw1 = su(dynp + OF_A1) + (unsigned)wid * 2048u;

    // ---- skip GEMM: Xhi@Whi + Xhi@Wlo + Xlo@Whi ----
    gemm16(aw0, su(dynp + OF_WHI), lane, acc);
    gemm16(aw0, su(dynp + OF_WLO), lane, acc);
    gemm16(aw1, su(dynp + OF_WHI), lane, acc);

    // ---- zero own A rows (warp-local: own skip-gemm reads are done) ----
    {
        uint4 z = {0, 0, 0, 0};
        uint4* r0 = reinterpret_cast<uint4*>(dynp + OF_A0 + rowo * 128 + half * 64);
        uint4* r1 = reinterpret_cast<uint4*>(dynp + OF_A1 + rowo * 128 + half * 64);
#pragma unroll
        for (int i = 0; i < 4; i++) { r0[i] = z; r1[i] = z; }
    }

    // ---- prologue basis: lanes<16 -> f=0 into A0, lanes>=16 -> f=1 into A1 ----
    int pw = -1;
    const float* xcol = X + (size_t)(rgbase + rowo) * NF;
    char* Ab = dynp + (half ? OF_A1 : OF_A0) + rowo * 128;
    write_basis(Ab, rx, xcol, half, sh_s, sc_s, kn, rcp6, pw);
    __syncwarp();
    asm volatile("cp.async.wait_group 0;");   // own slot 0-3 copies landed

    // ---- mainloop: 16 groups of 4 features; ONE __syncthreads per group ----
    for (int gq = 0; gq < 16; gq++) {
        __syncthreads();   // group gq's coef slots visible; prior group's reads done
        if (gq < 15) {
            int sb = ((gq + 1) & 1) * 4;
            int fb = 4 * (gq + 1);
            cpa_coef(dynp, sb + 0, fb + 0, tid);
            cpa_coef(dynp, sb + 1, fb + 1, tid);
            cpa_coef(dynp, sb + 2, fb + 2, tid);
            cpa_coef(dynp, sb + 3, fb + 3, tid);
        }
        asm volatile("cp.async.commit_group;");

        const unsigned cbase = su(dynp + OF_C(0)) + (unsigned)((gq & 1) * 4) * 8192u;
#pragma unroll
        for (int p = 0; p < 2; p++) {
            int f = 4 * gq + 2 * p;
            gemm16(aw0, cbase + (unsigned)(2 * p) * 8192u, lane, acc);
            gemm16(aw1, cbase + (unsigned)(2 * p + 1) * 8192u, lane, acc);
            if (f + 2 < NF) {   // warp-local JIT write for features f+2 (A0) / f+3 (A1)
                write_basis(Ab, rx, xcol, f + 2 + half, sh_s, sc_s, kn, rcp6, pw);
                __syncwarp();
            }
        }
        asm volatile("cp.async.wait_group 0;");   // own next-group copies landed
    }

    // ---- epilogue: LN + exact GELU straight from registers ----
    {
        float s0 = 0.f, q0 = 0.f, s1 = 0.f, q1 = 0.f;
        const int t2 = (lane & 3) * 2;
#pragma unroll
        for (int nt = 0; nt < 8; nt++) {
            int c = nt * 8 + t2;
            float a0 = acc[nt][0] + cb_s[c], a1 = acc[nt][1] + cb_s[c + 1];
            float a2 = acc[nt][2] + cb_s[c], a3 = acc[nt][3] + cb_s[c + 1];
            acc[nt][0] = a0; acc[nt][1] = a1; acc[nt][2] = a2; acc[nt][3] = a3;
            s0 += a0 + a1; q0 += a0 * a0 + a1 * a1;
            s1 += a2 + a3; q1 += a2 * a2 + a3 * a3;
        }
        s0 += __shfl_xor_sync(0xffffffffu, s0, 1);
        s0 += __shfl_xor_sync(0xffffffffu, s0, 2);
        q0 += __shfl_xor_sync(0xffffffffu, q0, 1);
        q0 += __shfl_xor_sync(0xffffffffu, q0, 2);
        s1 += __shfl_xor_sync(0xffffffffu, s1, 1);
        s1 += __shfl_xor_sync(0xffffffffu, s1, 2);
        q1 += __shfl_xor_sync(0xffffffffu, q1, 1);
        q1 += __shfl_xor_sync(0xffffffffu, q1, 2);
        float m0 = s0 * (1.0f / 64.0f);
        float v0 = fmaxf(q0 * (1.0f / 64.0f) - m0 * m0, 0.0f);
        float i0 = rsqrtf(v0 + 1e-5f);
        float m1 = s1 * (1.0f / 64.0f);
        float v1 = fmaxf(q1 * (1.0f / 64.0f) - m1 * m1, 0.0f);
        float i1 = rsqrtf(v1 + 1e-5f);

        const int r0 = rgbase + wid * 16 + (lane >> 2);
        float* o0 = out + (size_t)r0 * NW;
        float* o1 = o0 + 8 * NW;   // row r0 + 8
#pragma unroll
        for (int nt = 0; nt < 8; nt++) {
            int c = nt * 8 + t2;
            float z0 = (acc[nt][0] - m0) * i0 * ga_s[c] + be_s[c];
            float z1 = (acc[nt][1] - m0) * i0 * ga_s[c + 1] + be_s[c + 1];
            float z2 = (acc[nt][2] - m1) * i1 * ga_s[c] + be_s[c];
            float z3 = (acc[nt][3] - m1) * i1 * ga_s[c + 1] + be_s[c + 1];
            float2 w0, w1;
            w0.x = 0.5f * z0 * (1.0f + erff(z0 * 0.70710678118654752f));
            w0.y = 0.5f * z1 * (1.0f + erff(z1 * 0.70710678118654752f));
            w1.x = 0.5f * z2 * (1.0f + erff(z2 * 0.70710678118654752f));
            w1.y = 0.5f * z3 * (1.0f + erff(z3 * 0.70710678118654752f));
            *reinterpret_cast<float2*>(o0 + c) = w0;
            *reinterpret_cast<float2*>(o1 + c) = w1;
        }
    }
}

extern "C" void kernel_launch(void* const* d_in, const int* in_sizes, int n_in,
                              void* d_out, int out_size) {
    const float* X      = (const float*)d_in[0];
    const float* shift  = (const float*)d_in[1];
    const float* lscale = (const float*)d_in[2];
    const float* coef   = (const float*)d_in[3];
    const float* skipW  = (const float*)d_in[4];
    const float* skipb  = (const float*)d_in[5];
    const float* bias   = (const float*)d_in[6];
    const float* gam    = (const float*)d_in[7];
    const float* bet    = (const float*)d_in[8];
    const float* knots  = (const float*)d_in[9];

    cudaFuncSetAttribute(kan_kernel, cudaFuncAttributeMaxDynamicSharedMemorySize,
                         DYN_BYTES);

    prep_kernel<<<256, 256>>>(coef);
    kan_kernel<<<NCTA, NTHREADS, DYN_BYTES>>>(X, shift, lscale, skipW, skipb,
                                              bias, gam, bet, knots,
                                              (float*)d_out);
}